// round 4
// baseline (speedup 1.0000x reference)
#include <cuda_runtime.h>
#include <math.h>

// ---- ANI-1x constants ----
#define RCR 5.2f
#define RCA 3.5f
#define ETA_R 16.0f
#define ETA_A 8.0f
#define PI_F 3.14159265358979323846f
#define NMAX 256
#define NBINS_R 16
#define NBINS_A 32   // 4 ShfA * 8 ShfZ
#define AEV_W 384

__constant__ float c_shfA[4] = {0.9f, 1.55f, 2.2f, 2.85f};
// ShfZ = (2k+1)*pi/16 -> cos/sin are exact constants
__constant__ float c_cz[8]  = { 0.98078528f,  0.83146961f,  0.55557023f,  0.19509032f,
                               -0.19509032f, -0.55557023f, -0.83146961f, -0.98078528f};
__constant__ float c_sz[8]  = { 0.19509032f,  0.55557023f,  0.83146961f,  0.98078528f,
                                0.98078528f,  0.83146961f,  0.55557023f,  0.19509032f};

__global__ __launch_bounds__(256, 4)
void aev_kernel(const float* __restrict__ coords, float* __restrict__ out, int n) {
    const int i = blockIdx.x;
    const int tid = threadIdx.x;
    const int lane = tid & 31;

    __shared__ float sx[NMAX], sy[NMAX], sz[NMAX];
    __shared__ float nux[NMAX], nuy[NMAX], nuz[NMAX], nd[NMAX], nfc[NMAX];
    __shared__ int s_cnt;
    __shared__ float acc[NBINS_R + NBINS_A];

    if (tid == 0) s_cnt = 0;
    if (tid < NBINS_R + NBINS_A) acc[tid] = 0.0f;
    for (int j = tid; j < n; j += blockDim.x) {
        sx[j] = coords[3 * j + 0];
        sy[j] = coords[3 * j + 1];
        sz[j] = coords[3 * j + 2];
    }
    __syncthreads();

    const float cix = sx[i], ciy = sy[i], ciz = sz[i];

    // ---- radial pass + neighbor-list build ----
    for (int j = tid; j < n; j += blockDim.x) {
        if (j == i) continue;
        float dx = cix - sx[j];
        float dy = ciy - sy[j];
        float dz = ciz - sz[j];
        float d = sqrtf(dx * dx + dy * dy + dz * dz);
        if (d <= RCR) {
            float fc = 0.5f * cosf(PI_F * d / RCR) + 0.5f;
            #pragma unroll
            for (int k = 0; k < NBINS_R; k++) {
                float shr = 0.9f + 0.26875f * (float)k;  // linspace(0.9, 4.93125, 16)
                float t = d - shr;
                atomicAdd(&acc[k], 0.25f * __expf(-ETA_R * t * t) * fc);
            }
        }
        if (d <= RCA) {
            float fca = 0.5f * cosf(PI_F * d / RCA) + 0.5f;
            int idx = atomicAdd(&s_cnt, 1);
            float inv = 1.0f / d;
            nux[idx] = dx * inv;
            nuy[idx] = dy * inv;
            nuz[idx] = dz * inv;
            nd[idx] = d;
            nfc[idx] = fca;
        }
    }
    __syncthreads();
    const int M = s_cnt;

    // ---- angular pass: ordered (j,k), j != k, both within RCA ----
    float ang[NBINS_A];
    #pragma unroll
    for (int m = 0; m < NBINS_A; m++) ang[m] = 0.0f;

    const int MM = M * M;
    for (int p = tid; p < MM; p += blockDim.x) {
        int jj = p / M;
        int kk = p - jj * M;
        if (jj == kk) continue;
        float c = nux[jj] * nux[kk] + nuy[jj] * nuy[kk] + nuz[jj] * nuz[kk];
        float ct = 0.95f * c;                           // cos(theta), theta = acos(0.95 c)
        float st = sqrtf(fmaxf(1.0f - ct * ct, 0.0f));  // sin(theta) >= 0
        float davg = 0.5f * (nd[jj] + nd[kk]);
        float fcp = nfc[jj] * nfc[kk];
        float f2[4];
        #pragma unroll
        for (int a = 0; a < 4; a++) {
            float t = davg - c_shfA[a];
            f2[a] = __expf(-ETA_A * t * t) * fcp;
        }
        #pragma unroll
        for (int z = 0; z < 8; z++) {
            // cos(theta - shfZ) via identity; x = (1+cos)/2, x^32 by squaring
            float x = 0.5f * (1.0f + ct * c_cz[z] + st * c_sz[z]);
            float x2 = x * x;
            float x4 = x2 * x2;
            float x8 = x4 * x4;
            float x16 = x8 * x8;
            float x32 = x16 * x16;
            #pragma unroll
            for (int a = 0; a < 4; a++) {
                ang[a * 8 + z] += f2[a] * x32;
            }
        }
    }

    // warp-reduce the 32 angular bins, then one atomic per warp per bin
    #pragma unroll
    for (int m = 0; m < NBINS_A; m++) {
        float v = ang[m];
        v += __shfl_down_sync(0xFFFFFFFFu, v, 16);
        v += __shfl_down_sync(0xFFFFFFFFu, v, 8);
        v += __shfl_down_sync(0xFFFFFFFFu, v, 4);
        v += __shfl_down_sync(0xFFFFFFFFu, v, 2);
        v += __shfl_down_sync(0xFFFFFFFFu, v, 1);
        if (lane == 0 && v != 0.0f) atomicAdd(&acc[NBINS_R + m], v);
    }
    __syncthreads();

    // ---- write the full 384-wide AEV row (zeros in species padding) ----
    for (int c = tid; c < AEV_W; c += blockDim.x) {
        float v = 0.0f;
        if (c < NBINS_R) v = acc[c];                                        // radial species-0 block
        else if (c >= 64 && c < 64 + NBINS_A) v = acc[NBINS_R + (c - 64)];  // angular (0,0) block
        out[i * AEV_W + c] = v;
    }
}

extern "C" void kernel_launch(void* const* d_in, const int* in_sizes, int n_in,
                              void* d_out, int out_size) {
    const float* coords = (const float*)d_in[0];
    float* out = (float*)d_out;
    int n = in_sizes[0] / 3;
    aev_kernel<<<n, 256>>>(coords, out, n);
}

// round 6
// speedup vs baseline: 1.1792x; 1.1792x over previous
#include <cuda_runtime.h>
#include <math.h>

// ---- ANI-1x constants ----
#define RCR 5.2f
#define RCA 3.5f
#define ETA_R 16.0f
#define ETA_A 8.0f
#define PI_F 3.14159265358979323846f
#define NBMAX 256
#define AEV_W 384
#define SUBS 4          // sub-CTAs per atom
#define BLK 128
#define MAXIT 8         // supports n up to MAXIT*BLK = 1024

__constant__ float c_shfA[4] = {0.9f, 1.55f, 2.2f, 2.85f};
// ShfZ = (2k+1)*pi/16 -> cos/sin are exact constants
__constant__ float c_cz[8]  = { 0.98078528f,  0.83146961f,  0.55557023f,  0.19509032f,
                               -0.19509032f, -0.55557023f, -0.83146961f, -0.98078528f};
__constant__ float c_sz[8]  = { 0.19509032f,  0.55557023f,  0.83146961f,  0.98078528f,
                                0.98078528f,  0.83146961f,  0.55557023f,  0.19509032f};

__global__ void zero_kernel(float4* __restrict__ out4, int n4) {
    int t = blockIdx.x * blockDim.x + threadIdx.x;
    if (t < n4) out4[t] = make_float4(0.f, 0.f, 0.f, 0.f);
}

__global__ __launch_bounds__(BLK, 7)
void aev_kernel(const float* __restrict__ coords, float* __restrict__ out, int n) {
    const int sub = blockIdx.x & (SUBS - 1);
    const int i   = blockIdx.x >> 2;
    const int tid  = threadIdx.x;
    const int lane = tid & 31;
    const int wid  = tid >> 5;

    __shared__ float nux[NBMAX], nuy[NBMAX], nuz[NBMAX], nd[NBMAX], nfc[NBMAX];
    __shared__ int cnt[MAXIT * 4];     // per (iteration, warp) neighbor counts -> exclusive offsets
    __shared__ float accr[16];
    __shared__ float acca[32];
    __shared__ int s_tot;

    if (tid < 16) accr[tid] = 0.f;
    if (tid < 32) acca[tid] = 0.f;

    const float cix = coords[3 * i + 0];
    const float ciy = coords[3 * i + 1];
    const float ciz = coords[3 * i + 2];

    const int niter = (n + BLK - 1) / BLK;

    // ---- pass 1: count RCA-neighbors per (iter, warp) [deterministic across subs] ----
    for (int it = 0; it < niter; it++) {
        int j = it * BLK + tid;
        bool nb = false;
        if (j < n && j != i) {
            float dx = cix - coords[3 * j + 0];
            float dy = ciy - coords[3 * j + 1];
            float dz = ciz - coords[3 * j + 2];
            float d2 = dx * dx + dy * dy + dz * dz;
            nb = (d2 <= RCA * RCA);
        }
        unsigned b = __ballot_sync(0xFFFFFFFFu, nb);
        if (lane == 0) cnt[it * 4 + wid] = __popc(b);
    }
    __syncthreads();
    if (tid == 0) {
        int s = 0;
        for (int e = 0; e < niter * 4; e++) { int c = cnt[e]; cnt[e] = s; s += c; }
        s_tot = s;
    }
    __syncthreads();
    const int M = s_tot;

    // ---- pass 2: write compacted neighbor list in deterministic j-order; radial (1/4 share) ----
    for (int it = 0; it < niter; it++) {
        int j = it * BLK + tid;
        bool valid = (j < n && j != i);
        float dx = 0.f, dy = 0.f, dz = 0.f, d = 1.0f;
        if (valid) {
            dx = cix - coords[3 * j + 0];
            dy = ciy - coords[3 * j + 1];
            dz = ciz - coords[3 * j + 2];
            d = sqrtf(dx * dx + dy * dy + dz * dz);
        }
        bool nb = valid && (d <= RCA);
        unsigned b = __ballot_sync(0xFFFFFFFFu, nb);
        if (nb) {
            int idx = cnt[it * 4 + wid] + __popc(b & ((1u << lane) - 1u));
            float inv = 1.0f / d;
            nux[idx] = dx * inv;
            nuy[idx] = dy * inv;
            nuz[idx] = dz * inv;
            nd[idx] = d;
            nfc[idx] = 0.5f * __cosf(PI_F * (1.0f / RCA) * d) + 0.5f;
        }
        if (valid && d <= RCR && ((j & (SUBS - 1)) == sub)) {
            float fcr = 0.25f * (0.5f * __cosf(PI_F * (1.0f / RCR) * d) + 0.5f);
            #pragma unroll
            for (int k = 0; k < 16; k++) {
                float t = d - (0.9f + 0.26875f * (float)k);  // linspace(0.9, 4.93125, 16)
                atomicAdd(&accr[k], __expf(-ETA_R * t * t) * fcr);
            }
        }
    }
    __syncthreads();
    const int T = (M * (M - 1)) >> 1;   // unordered pairs j<k

    // ---- angular: j<k triangle, strided across 4 subs x 128 threads ----
    float ang[32];
    #pragma unroll
    for (int m = 0; m < 32; m++) ang[m] = 0.f;

    for (int p = sub * BLK + tid; p < T; p += SUBS * BLK) {
        // triangle decode: jj s.t. jj(jj-1)/2 <= p < jj(jj+1)/2
        int jj = (int)(0.5f * (1.0f + sqrtf(8.0f * (float)p + 1.0f)));
        while (((jj * (jj - 1)) >> 1) > p) --jj;
        while ((((jj + 1) * jj) >> 1) <= p) ++jj;
        int kk = p - ((jj * (jj - 1)) >> 1);

        float c  = nux[jj] * nux[kk] + nuy[jj] * nuy[kk] + nuz[jj] * nuz[kk];
        float ct = 0.95f * c;                           // cos(theta), theta = acos(0.95 c)
        float st = sqrtf(fmaxf(1.0f - ct * ct, 0.0f));  // sin(theta) >= 0 on [0,pi]
        float davg = 0.5f * (nd[jj] + nd[kk]);
        float fcp  = nfc[jj] * nfc[kk];
        float f2[4];
        #pragma unroll
        for (int a = 0; a < 4; a++) {
            float t = davg - c_shfA[a];
            f2[a] = __expf(-ETA_A * t * t) * fcp;       // 4 independent MUFU chains
        }
        #pragma unroll
        for (int z = 0; z < 8; z++) {
            // cos(theta - ShfZ) = ct*cos(ShfZ) + st*sin(ShfZ); x = (1+cos)/2; x^32 by squaring
            float x = 0.5f + 0.5f * (ct * c_cz[z] + st * c_sz[z]);
            float x2 = x * x, x4 = x2 * x2, x8 = x4 * x4, x16 = x8 * x8, x32 = x16 * x16;
            #pragma unroll
            for (int a = 0; a < 4; a++) ang[a * 8 + z] += f2[a] * x32;
        }
    }

    // ---- reduce: warp shuffle -> SMEM -> global atomics ----
    #pragma unroll
    for (int m = 0; m < 32; m++) {
        float v = ang[m];
        v += __shfl_down_sync(0xFFFFFFFFu, v, 16);
        v += __shfl_down_sync(0xFFFFFFFFu, v, 8);
        v += __shfl_down_sync(0xFFFFFFFFu, v, 4);
        v += __shfl_down_sync(0xFFFFFFFFu, v, 2);
        v += __shfl_down_sync(0xFFFFFFFFu, v, 1);
        if (lane == 0 && v != 0.f) atomicAdd(&acca[m], v);
    }
    __syncthreads();

    if (tid < 16 && accr[tid] != 0.f)
        atomicAdd(&out[i * AEV_W + tid], accr[tid]);
    if (tid < 32 && acca[tid] != 0.f)
        atomicAdd(&out[i * AEV_W + 64 + tid], 2.0f * acca[tid]);  // ordered sum = 2 * (j<k) sum
}

extern "C" void kernel_launch(void* const* d_in, const int* in_sizes, int n_in,
                              void* d_out, int out_size) {
    const float* coords = (const float*)d_in[0];
    float* out = (float*)d_out;
    int n = in_sizes[0] / 3;
    int n4 = out_size / 4;   // 384 % 4 == 0
    zero_kernel<<<(n4 + 255) / 256, 256>>>((float4*)d_out, n4);
    aev_kernel<<<n * SUBS, BLK>>>(coords, out, n);
}

// round 7
// speedup vs baseline: 1.6875x; 1.4310x over previous
#include <cuda_runtime.h>
#include <math.h>

// ---- ANI-1x constants ----
#define RCR 5.2f
#define RCA 3.5f
#define ETA_R 16.0f
#define ETA_A 8.0f
#define PI_F 3.14159265358979323846f
#define AEV_W 384
#define SUBS 4            // sub-CTAs per atom
#define BLK 256           // 8 warps
#define NWARP 8
#define GW (SUBS * NWARP) // 32 warps cooperating per atom
#define NATMAX 512        // staged coords capacity
#define NBMAX 256         // neighbor list capacity
#define MAXIT 2           // build iterations: n <= MAXIT*BLK

__constant__ float c_shfA[4] = {0.9f, 1.55f, 2.2f, 2.85f};
// ShfZ = (2k+1)*pi/16 -> cos/sin are exact constants
__constant__ float c_cz[8]  = { 0.98078528f,  0.83146961f,  0.55557023f,  0.19509032f,
                               -0.19509032f, -0.55557023f, -0.83146961f, -0.98078528f};
__constant__ float c_sz[8]  = { 0.19509032f,  0.55557023f,  0.83146961f,  0.98078528f,
                                0.98078528f,  0.83146961f,  0.55557023f,  0.19509032f};

__global__ void zero_kernel(float4* __restrict__ out4, int n4) {
    int t = blockIdx.x * blockDim.x + threadIdx.x;
    if (t < n4) out4[t] = make_float4(0.f, 0.f, 0.f, 0.f);
}

__global__ __launch_bounds__(BLK, 6)
void aev_kernel(const float* __restrict__ coords, float* __restrict__ out, int n) {
    const int sub  = blockIdx.x & (SUBS - 1);
    const int i    = blockIdx.x >> 2;
    const int tid  = threadIdx.x;
    const int lane = tid & 31;
    const int wid  = tid >> 5;
    const int gw   = sub * NWARP + wid;      // global warp id for atom i: 0..GW-1

    __shared__ float sx[NATMAX], sy[NATMAX], sz[NATMAX];
    __shared__ float nux[NBMAX], nuy[NBMAX], nuz[NBMAX], nd[NBMAX], nfc[NBMAX];
    __shared__ int cnt[MAXIT * NWARP];
    __shared__ int s_tot;

    // ---- stage coords ----
    for (int j = tid; j < n; j += BLK) {
        sx[j] = coords[3 * j + 0];
        sy[j] = coords[3 * j + 1];
        sz[j] = coords[3 * j + 2];
    }
    __syncthreads();

    const float cix = sx[i], ciy = sy[i], ciz = sz[i];
    const int niter = (n + BLK - 1) / BLK;

    // ---- pass 1: count RCA neighbors per (iter, warp) [deterministic across subs] ----
    for (int it = 0; it < niter; it++) {
        int j = it * BLK + tid;
        bool nb = false;
        if (j < n && j != i) {
            float dx = cix - sx[j], dy = ciy - sy[j], dz = ciz - sz[j];
            nb = (dx * dx + dy * dy + dz * dz <= RCA * RCA);
        }
        unsigned b = __ballot_sync(0xFFFFFFFFu, nb);
        if (lane == 0) cnt[it * NWARP + wid] = __popc(b);
    }
    __syncthreads();
    if (tid == 0) {
        int s = 0;
        for (int e = 0; e < niter * NWARP; e++) { int c = cnt[e]; cnt[e] = s; s += c; }
        s_tot = s;
    }
    __syncthreads();
    const int M = s_tot;

    // ---- pass 2: compacted neighbor list in deterministic j-order ----
    for (int it = 0; it < niter; it++) {
        int j = it * BLK + tid;
        bool nb = false;
        float dx = 0.f, dy = 0.f, dz = 0.f, d2 = 1.f;
        if (j < n && j != i) {
            dx = cix - sx[j]; dy = ciy - sy[j]; dz = ciz - sz[j];
            d2 = dx * dx + dy * dy + dz * dz;
            nb = (d2 <= RCA * RCA);
        }
        unsigned b = __ballot_sync(0xFFFFFFFFu, nb);
        if (nb) {
            int idx = cnt[it * NWARP + wid] + __popc(b & ((1u << lane) - 1u));
            float d = sqrtf(d2);
            float inv = 1.0f / d;
            nux[idx] = dx * inv;
            nuy[idx] = dy * inv;
            nuz[idx] = dz * inv;
            nd[idx]  = d;
            nfc[idx] = 0.5f * __cosf(PI_F * (1.0f / RCA) * d) + 0.5f;
        }
    }
    __syncthreads();

    // ---- radial: bin-per-lane (lanes 0-15 and 16-31 handle two j's per iter) ----
    {
        const int h = lane >> 4;                 // which j this half-warp handles
        const float shr = 0.9f + 0.26875f * (float)(lane & 15);
        float racc = 0.f;
        const int nq = (n + GW - 1) / GW;        // multipliers needed to cover all j
        for (int it = 0; 2 * it + 1 <= nq; it++) {
            int j = (2 * it + h) * GW + gw;
            bool valid = (j < n) && (j != i);
            int js = valid ? j : 0;
            float dx = cix - sx[js], dy = ciy - sy[js], dz = ciz - sz[js];
            float d = sqrtf(dx * dx + dy * dy + dz * dz);
            bool inr = valid && (d <= RCR);
            float fcr = 0.5f * __cosf(PI_F * (1.0f / RCR) * d) + 0.5f;
            float t = d - shr;
            float v = 0.25f * __expf(-ETA_R * t * t) * fcr;
            racc += inr ? v : 0.f;
        }
        racc += __shfl_xor_sync(0xFFFFFFFFu, racc, 16);
        if (lane < 16 && racc != 0.f)
            atomicAdd(&out[i * AEV_W + lane], racc);
    }

    // ---- angular: one pair per warp, bin-per-lane; j<k triangle (x2 at the end) ----
    {
        const float czL = c_cz[lane & 7];
        const float szL = c_sz[lane & 7];
        const float saL = c_shfA[lane >> 3];
        float aacc = 0.f;
        const int T = (M * (M - 1)) >> 1;
        #pragma unroll 2
        for (int p = gw; p < T; p += GW) {
            // warp-uniform triangle decode: jj s.t. jj(jj-1)/2 <= p < jj(jj+1)/2
            int jj = (int)(0.5f * (1.0f + sqrtf(8.0f * (float)p + 1.0f)));
            while (((jj * (jj - 1)) >> 1) > p) --jj;
            while ((((jj + 1) * jj) >> 1) <= p) ++jj;
            int kk = p - ((jj * (jj - 1)) >> 1);

            float ct = 0.95f * (nux[jj] * nux[kk] + nuy[jj] * nuy[kk] + nuz[jj] * nuz[kk]);
            float st = sqrtf(fmaxf(1.0f - ct * ct, 0.0f));   // sin(acos(ct)) >= 0
            float davg = 0.5f * (nd[jj] + nd[kk]);
            float fcp  = nfc[jj] * nfc[kk];
            // cos(theta - ShfZ) = ct*cos(ShfZ) + st*sin(ShfZ); x = (1+cos)/2; x^32 by squaring
            float x = 0.5f + 0.5f * (ct * czL + st * szL);
            float x2 = x * x, x4 = x2 * x2, x8 = x4 * x4, x16 = x8 * x8, x32 = x16 * x16;
            float t = davg - saL;
            aacc += fcp * __expf(-ETA_A * t * t) * x32;
        }
        if (aacc != 0.f)
            atomicAdd(&out[i * AEV_W + 64 + lane], 2.0f * aacc);  // ordered sum = 2 * (j<k) sum
    }
}

extern "C" void kernel_launch(void* const* d_in, const int* in_sizes, int n_in,
                              void* d_out, int out_size) {
    const float* coords = (const float*)d_in[0];
    float* out = (float*)d_out;
    int n = in_sizes[0] / 3;
    int n4 = out_size / 4;   // 384 % 4 == 0
    zero_kernel<<<(n4 + 255) / 256, 256>>>((float4*)d_out, n4);
    aev_kernel<<<n * SUBS, BLK>>>(coords, out, n);
}

// round 8
// speedup vs baseline: 1.9575x; 1.1600x over previous
#include <cuda_runtime.h>
#include <math.h>

// ---- ANI-1x constants ----
#define RCR 5.2f
#define RCA 3.5f
#define ETA_R 16.0f
#define ETA_A 8.0f
#define PI_F 3.14159265358979323846f
#define AEV_W 384
#define SUBS 4            // sub-CTAs per atom
#define BLK 256           // 8 warps
#define NWARP 8
#define GW (SUBS * NWARP) // 32 warps cooperating per atom
#define NATMAX 512        // staged coords capacity
#define NBMAX 256         // neighbor list capacity
#define MAXIT 2           // build iterations: n <= MAXIT*BLK

__constant__ float c_shfA[4] = {0.9f, 1.55f, 2.2f, 2.85f};
// ShfZ = (2k+1)*pi/16 -> cos/sin are exact constants
__constant__ float c_cz[8]  = { 0.98078528f,  0.83146961f,  0.55557023f,  0.19509032f,
                               -0.19509032f, -0.55557023f, -0.83146961f, -0.98078528f};
__constant__ float c_sz[8]  = { 0.19509032f,  0.55557023f,  0.83146961f,  0.98078528f,
                                0.98078528f,  0.83146961f,  0.55557023f,  0.19509032f};

__global__ void zero_kernel(float4* __restrict__ out4, int n4) {
    int t = blockIdx.x * blockDim.x + threadIdx.x;
    if (t < n4) out4[t] = make_float4(0.f, 0.f, 0.f, 0.f);
}

__global__ __launch_bounds__(BLK, 6)
void aev_kernel(const float* __restrict__ coords, float* __restrict__ out, int n) {
    const int sub  = blockIdx.x & (SUBS - 1);
    const int i    = blockIdx.x >> 2;
    const int tid  = threadIdx.x;
    const int lane = tid & 31;
    const int wid  = tid >> 5;
    const int gw   = sub * NWARP + wid;      // global warp id for atom i: 0..GW-1

    __shared__ float sx[NATMAX], sy[NATMAX], sz[NATMAX];
    __shared__ float nux[NBMAX], nuy[NBMAX], nuz[NBMAX], nd[NBMAX], nfc[NBMAX];
    __shared__ int cnt[MAXIT * NWARP];
    __shared__ int s_tot;

    // ---- stage coords ----
    for (int j = tid; j < n; j += BLK) {
        sx[j] = coords[3 * j + 0];
        sy[j] = coords[3 * j + 1];
        sz[j] = coords[3 * j + 2];
    }
    __syncthreads();

    const float cix = sx[i], ciy = sy[i], ciz = sz[i];
    const int niter = (n + BLK - 1) / BLK;

    // ---- pass 1: count RCA neighbors per (iter, warp) [deterministic across subs] ----
    for (int it = 0; it < niter; it++) {
        int j = it * BLK + tid;
        bool nb = false;
        if (j < n && j != i) {
            float dx = cix - sx[j], dy = ciy - sy[j], dz = ciz - sz[j];
            nb = (dx * dx + dy * dy + dz * dz <= RCA * RCA);
        }
        unsigned b = __ballot_sync(0xFFFFFFFFu, nb);
        if (lane == 0) cnt[it * NWARP + wid] = __popc(b);
    }
    __syncthreads();
    if (tid == 0) {
        int s = 0;
        for (int e = 0; e < niter * NWARP; e++) { int c = cnt[e]; cnt[e] = s; s += c; }
        s_tot = s;
    }
    __syncthreads();
    const int M = s_tot;

    // ---- pass 2: compacted neighbor list in deterministic j-order ----
    for (int it = 0; it < niter; it++) {
        int j = it * BLK + tid;
        bool nb = false;
        float dx = 0.f, dy = 0.f, dz = 0.f, d2 = 1.f;
        if (j < n && j != i) {
            dx = cix - sx[j]; dy = ciy - sy[j]; dz = ciz - sz[j];
            d2 = dx * dx + dy * dy + dz * dz;
            nb = (d2 <= RCA * RCA);
        }
        unsigned b = __ballot_sync(0xFFFFFFFFu, nb);
        if (nb) {
            int idx = cnt[it * NWARP + wid] + __popc(b & ((1u << lane) - 1u));
            float d = sqrtf(d2);
            float inv = 1.0f / d;
            nux[idx] = dx * inv;
            nuy[idx] = dy * inv;
            nuz[idx] = dz * inv;
            nd[idx]  = d;
            nfc[idx] = 0.5f * __cosf(PI_F * (1.0f / RCA) * d) + 0.5f;
        }
    }
    __syncthreads();

    // ---- radial: bin-per-lane (lanes 0-15 and 16-31 handle two j's per iter) ----
    {
        const int h = lane >> 4;                 // which j this half-warp handles
        const float shr = 0.9f + 0.26875f * (float)(lane & 15);
        float racc = 0.f;
        const int nq = (n + GW - 1) / GW;
        for (int it = 0; 2 * it + 1 <= nq; it++) {
            int j = (2 * it + h) * GW + gw;
            bool valid = (j < n) && (j != i);
            int js = valid ? j : 0;
            float dx = cix - sx[js], dy = ciy - sy[js], dz = ciz - sz[js];
            float d = sqrtf(dx * dx + dy * dy + dz * dz);
            bool inr = valid && (d <= RCR);
            float fcr = 0.5f * __cosf(PI_F * (1.0f / RCR) * d) + 0.5f;
            float t = d - shr;
            float v = 0.25f * __expf(-ETA_R * t * t) * fcr;
            racc += inr ? v : 0.f;
        }
        racc += __shfl_xor_sync(0xFFFFFFFFu, racc, 16);
        if (lane < 16 && racc != 0.f)
            atomicAdd(&out[i * AEV_W + lane], racc);
    }

    // ---- angular: 4 pairs per warp iteration (pg = lane>>3), 8 zeta-bins per group,
    //      4 ShfA accumulators per lane; j<k triangle (x2 at the end) ----
    {
        const int pg = lane >> 3;
        const int z  = lane & 7;
        const float czL = c_cz[z];
        const float szL = c_sz[z];
        float a0 = 0.f, a1 = 0.f, a2 = 0.f, a3 = 0.f;
        const int T = (M * (M - 1)) >> 1;

        for (int p0 = gw * 4; p0 < T; p0 += GW * 4) {
            int p = p0 + pg;
            bool ok = (p < T);
            int pc = ok ? p : 0;
            // triangle decode: jj s.t. jj(jj-1)/2 <= pc < jj(jj+1)/2 (uniform within pg group)
            int jj = (int)(0.5f * (1.0f + sqrtf(8.0f * (float)pc + 1.0f)));
            while (((jj * (jj - 1)) >> 1) > pc) --jj;
            while ((((jj + 1) * jj) >> 1) <= pc) ++jj;
            int kk = pc - ((jj * (jj - 1)) >> 1);

            float ct = 0.95f * (nux[jj] * nux[kk] + nuy[jj] * nuy[kk] + nuz[jj] * nuz[kk]);
            float st = sqrtf(fmaxf(1.0f - ct * ct, 0.0f));   // sin(acos(ct)) >= 0
            float davg = 0.5f * (nd[jj] + nd[kk]);
            float g = ok ? (nfc[jj] * nfc[kk]) : 0.f;
            // cos(theta - ShfZ) = ct*cos + st*sin; x = (1+cos)/2; x^32 by squaring
            float x = 0.5f + 0.5f * (ct * czL + st * szL);
            float x2 = x * x, x4 = x2 * x2, x8 = x4 * x4, x16 = x8 * x8;
            g *= x16 * x16;                                  // fcp * x^32, shared by the 4 exps
            float t0 = davg - 0.9f;
            float t1 = davg - 1.55f;
            float t2 = davg - 2.2f;
            float t3 = davg - 2.85f;
            a0 += g * __expf(-ETA_A * t0 * t0);
            a1 += g * __expf(-ETA_A * t1 * t1);
            a2 += g * __expf(-ETA_A * t2 * t2);
            a3 += g * __expf(-ETA_A * t3 * t3);
        }

        // reduce across the 4 pair-groups (pg): xor-8 then xor-16
        a0 += __shfl_xor_sync(0xFFFFFFFFu, a0, 8);
        a0 += __shfl_xor_sync(0xFFFFFFFFu, a0, 16);
        a1 += __shfl_xor_sync(0xFFFFFFFFu, a1, 8);
        a1 += __shfl_xor_sync(0xFFFFFFFFu, a1, 16);
        a2 += __shfl_xor_sync(0xFFFFFFFFu, a2, 8);
        a2 += __shfl_xor_sync(0xFFFFFFFFu, a2, 16);
        a3 += __shfl_xor_sync(0xFFFFFFFFu, a3, 8);
        a3 += __shfl_xor_sync(0xFFFFFFFFu, a3, 16);

        if (lane < 8) {   // lane z holds bins (a, z); ordered sum = 2 * (j<k) sum
            float* orow = &out[i * AEV_W + 64];
            if (a0 != 0.f) atomicAdd(&orow[0 * 8 + lane], 2.0f * a0);
            if (a1 != 0.f) atomicAdd(&orow[1 * 8 + lane], 2.0f * a1);
            if (a2 != 0.f) atomicAdd(&orow[2 * 8 + lane], 2.0f * a2);
            if (a3 != 0.f) atomicAdd(&orow[3 * 8 + lane], 2.0f * a3);
        }
    }
}

extern "C" void kernel_launch(void* const* d_in, const int* in_sizes, int n_in,
                              void* d_out, int out_size) {
    const float* coords = (const float*)d_in[0];
    float* out = (float*)d_out;
    int n = in_sizes[0] / 3;
    int n4 = out_size / 4;   // 384 % 4 == 0
    zero_kernel<<<(n4 + 255) / 256, 256>>>((float4*)d_out, n4);
    aev_kernel<<<n * SUBS, BLK>>>(coords, out, n);
}

// round 9
// speedup vs baseline: 2.3304x; 1.1905x over previous
#include <cuda_runtime.h>
#include <math.h>

// ---- ANI-1x constants ----
#define RCR 5.2f
#define RCA 3.5f
#define ETA_R 16.0f
#define ETA_A 8.0f
#define PI_F 3.14159265358979323846f
#define AEV_W 384
#define BLK 1024
#define NW 32            // warps per CTA (= warps per atom)
#define NATMAX 1024
#define NBMAX 512

// Gaussian recurrence over the 4 equally spaced ShfA (0.9,1.55,2.2,2.85; delta=0.65):
// e_a = exp(-eta*(t0 - a*delta)^2) = e0 * r^a * q^(a^2),  r = exp(2*eta*delta*t0), q = exp(-eta*delta^2)
#define QA   0.03404745f      // exp(-8*0.65^2) = exp(-3.38)
#define QA2  0.001159229f     // QA^2
#define TWO_ETA_D 10.4f       // 2*8*0.65

// ShfZ = (2k+1)*pi/16 -> cos/sin are exact constants
__constant__ float c_cz[8]  = { 0.98078528f,  0.83146961f,  0.55557023f,  0.19509032f,
                               -0.19509032f, -0.55557023f, -0.83146961f, -0.98078528f};
__constant__ float c_sz[8]  = { 0.19509032f,  0.55557023f,  0.83146961f,  0.98078528f,
                                0.98078528f,  0.83146961f,  0.55557023f,  0.19509032f};

__global__ __launch_bounds__(BLK, 2)
void aev_kernel(const float* __restrict__ coords, float* __restrict__ out, int n) {
    const int i    = blockIdx.x;
    const int tid  = threadIdx.x;
    const int lane = tid & 31;
    const int wid  = tid >> 5;

    __shared__ float4 s_xyz[NATMAX];      // staged coords
    __shared__ float4 s_nbr[NBMAX];       // neighbor (ux,uy,uz,d)
    __shared__ float  s_fc[NBMAX];        // neighbor fc(RCA)
    __shared__ int    s_cnt[NW];
    __shared__ int    s_tot;
    __shared__ float  sm_red[NW * 17];    // radial staging, padded
    __shared__ float  sm_ang[NW * 33];    // angular staging, padded
    __shared__ float  fin[48];

    // ---- stage coords as float4 ----
    if (tid < n) {
        s_xyz[tid] = make_float4(coords[3 * tid + 0], coords[3 * tid + 1],
                                 coords[3 * tid + 2], 0.f);
    }
    __syncthreads();

    const float cix = s_xyz[i].x, ciy = s_xyz[i].y, ciz = s_xyz[i].z;

    // ---- build compacted RCA neighbor list (single pass, n <= BLK) ----
    bool nb = false;
    float dx = 0.f, dy = 0.f, dz = 0.f, d2 = 1.f;
    if (tid < n && tid != i) {
        float4 P = s_xyz[tid];
        dx = cix - P.x; dy = ciy - P.y; dz = ciz - P.z;
        d2 = dx * dx + dy * dy + dz * dz;
        nb = (d2 <= RCA * RCA);
    }
    unsigned bal = __ballot_sync(0xFFFFFFFFu, nb);
    if (lane == 0) s_cnt[wid] = __popc(bal);
    __syncthreads();
    if (wid == 0) {                         // exclusive scan of the 32 warp counts
        int c = s_cnt[lane];
        int s = c;
        #pragma unroll
        for (int o = 1; o < 32; o <<= 1) {
            int t = __shfl_up_sync(0xFFFFFFFFu, s, o);
            if (lane >= o) s += t;
        }
        s_cnt[lane] = s - c;
        if (lane == 31) s_tot = s;
    }
    __syncthreads();
    const int M = s_tot;
    if (nb) {
        int idx = s_cnt[wid] + __popc(bal & ((1u << lane) - 1u));
        float d = sqrtf(d2);
        float inv = 1.0f / d;
        s_nbr[idx] = make_float4(dx * inv, dy * inv, dz * inv, d);
        s_fc[idx]  = 0.5f * __cosf(PI_F * (1.0f / RCA) * d) + 0.5f;
    }
    __syncthreads();

    // ---- radial: bin-per-lane; each warp covers 2 j's per iter (half-warp split) ----
    {
        const int h = lane >> 4;
        const float shr = 0.9f + 0.26875f * (float)(lane & 15);
        float racc = 0.f;
        for (int it = 0; it * 2 * NW < n; it++) {
            int j = (2 * it + h) * NW + wid;
            bool valid = (j < n) && (j != i);
            int js = valid ? j : 0;
            float4 P = s_xyz[js];
            float ex = cix - P.x, ey = ciy - P.y, ez = ciz - P.z;
            float d = sqrtf(ex * ex + ey * ey + ez * ez);
            bool inr = valid && (d <= RCR);
            float fcr = 0.5f * __cosf(PI_F * (1.0f / RCR) * d) + 0.5f;
            float t = d - shr;
            float v = 0.25f * __expf(-ETA_R * t * t) * fcr;
            racc += inr ? v : 0.f;
        }
        racc += __shfl_xor_sync(0xFFFFFFFFu, racc, 16);
        if (lane < 16) sm_red[wid * 17 + lane] = racc;
    }

    // ---- angular: 4 pairs/warp-iter (pg = lane>>3), 8 zeta-bins/group, 4 ShfA accs ----
    {
        const int pg = lane >> 3;
        const int z  = lane & 7;
        const float czL = c_cz[z];
        const float szL = c_sz[z];
        float a0 = 0.f, a1 = 0.f, a2 = 0.f, a3 = 0.f;
        const int T = (M * (M - 1)) >> 1;   // unordered pairs j<k

        for (int p0 = wid * 4; p0 < T; p0 += NW * 4) {
            int p = p0 + pg;
            bool ok = (p < T);
            int pc = ok ? p : 0;
            // triangle decode: jj s.t. jj(jj-1)/2 <= pc < jj(jj+1)/2
            int jj = (int)(0.5f * (1.0f + sqrtf(8.0f * (float)pc + 1.0f)));
            while (((jj * (jj - 1)) >> 1) > pc) --jj;
            while ((((jj + 1) * jj) >> 1) <= pc) ++jj;
            int kk = pc - ((jj * (jj - 1)) >> 1);

            float4 J = s_nbr[jj];
            float4 K = s_nbr[kk];
            float ct = 0.95f * (J.x * K.x + J.y * K.y + J.z * K.z);
            float st = sqrtf(fmaxf(1.0f - ct * ct, 0.0f));   // sin(acos(ct)) >= 0
            float davg = 0.5f * (J.w + K.w);
            float g = ok ? (s_fc[jj] * s_fc[kk]) : 0.f;
            // cos(theta - ShfZ) = ct*cos + st*sin; x = (1+cos)/2; x^32 by squaring
            float x = 0.5f + 0.5f * (ct * czL + st * szL);
            float x2 = x * x, x4 = x2 * x2, x8 = x4 * x4, x16 = x8 * x8;
            g *= x16 * x16;                                  // fcp * x^32
            // 4 Gaussians from 2 exps via the recurrence
            float t0 = davg - 0.9f;
            float e0 = __expf(-ETA_A * t0 * t0);
            float r  = __expf(TWO_ETA_D * t0);
            float m1 = r * QA;
            float e1 = e0 * m1;
            float m2 = m1 * QA2;
            float e2 = e1 * m2;
            float m3 = m2 * QA2;
            float e3 = e2 * m3;
            a0 += g * e0;
            a1 += g * e1;
            a2 += g * e2;
            a3 += g * e3;
        }

        // fold the 4 pair-groups; lanes 0-7 then hold bins (a, z=lane)
        a0 += __shfl_xor_sync(0xFFFFFFFFu, a0, 8);
        a0 += __shfl_xor_sync(0xFFFFFFFFu, a0, 16);
        a1 += __shfl_xor_sync(0xFFFFFFFFu, a1, 8);
        a1 += __shfl_xor_sync(0xFFFFFFFFu, a1, 16);
        a2 += __shfl_xor_sync(0xFFFFFFFFu, a2, 8);
        a2 += __shfl_xor_sync(0xFFFFFFFFu, a2, 16);
        a3 += __shfl_xor_sync(0xFFFFFFFFu, a3, 8);
        a3 += __shfl_xor_sync(0xFFFFFFFFu, a3, 16);
        if (lane < 8) {
            sm_ang[wid * 33 + 0  + lane] = a0;
            sm_ang[wid * 33 + 8  + lane] = a1;
            sm_ang[wid * 33 + 16 + lane] = a2;
            sm_ang[wid * 33 + 24 + lane] = a3;
        }
    }
    __syncthreads();

    // ---- cross-warp reductions (deterministic, conflict-free via padding) ----
    if (wid < 16) {                 // radial: warp w reduces bin w over 32 source warps
        float v = sm_red[lane * 17 + wid];
        v += __shfl_xor_sync(0xFFFFFFFFu, v, 1);
        v += __shfl_xor_sync(0xFFFFFFFFu, v, 2);
        v += __shfl_xor_sync(0xFFFFFFFFu, v, 4);
        v += __shfl_xor_sync(0xFFFFFFFFu, v, 8);
        v += __shfl_xor_sync(0xFFFFFFFFu, v, 16);
        if (lane == 0) fin[wid] = v;
    }
    {                               // angular: warp w reduces bin w over 32 source warps
        float v = sm_ang[lane * 33 + wid];
        v += __shfl_xor_sync(0xFFFFFFFFu, v, 1);
        v += __shfl_xor_sync(0xFFFFFFFFu, v, 2);
        v += __shfl_xor_sync(0xFFFFFFFFu, v, 4);
        v += __shfl_xor_sync(0xFFFFFFFFu, v, 8);
        v += __shfl_xor_sync(0xFFFFFFFFu, v, 16);
        if (lane == 0) fin[16 + wid] = v;
    }
    __syncthreads();

    // ---- write the full 384-wide row, zeros in species padding ----
    if (tid < AEV_W) {
        float v = 0.f;
        if (tid < 16) v = fin[tid];
        else if (tid >= 64 && tid < 96) v = 2.0f * fin[16 + (tid - 64)];  // ordered = 2*(j<k)
        out[i * AEV_W + tid] = v;
    }
}

extern "C" void kernel_launch(void* const* d_in, const int* in_sizes, int n_in,
                              void* d_out, int out_size) {
    const float* coords = (const float*)d_in[0];
    float* out = (float*)d_out;
    int n = in_sizes[0] / 3;
    aev_kernel<<<n, BLK>>>(coords, out, n);
}

// round 10
// speedup vs baseline: 2.3373x; 1.0030x over previous
#include <cuda_runtime.h>
#include <math.h>

// ---- ANI-1x constants ----
#define RCR 5.2f
#define RCA 3.5f
#define ETA_R 16.0f
#define ETA_A 8.0f
#define PI_F 3.14159265358979323846f
#define AEV_W 384
#define BLK 1024
#define HALF_T 512        // threads per half (one atom per half)
#define HWN 16            // warps per half
#define NATMAX 512
#define NBMAX2 256

// Gaussian recurrence over the 4 equally spaced ShfA (0.9,1.55,2.2,2.85; delta=0.65):
// e_a = e0 * r^a * q^(a^2),  r = exp(2*eta*delta*t0), q = exp(-eta*delta^2)
#define QA   0.03404745f      // exp(-8*0.65^2)
#define QA2  0.001159229f     // QA^2
#define TWO_ETA_D 10.4f       // 2*8*0.65

// ShfZ = (2k+1)*pi/16 -> cos/sin are exact constants
__constant__ float c_cz[8]  = { 0.98078528f,  0.83146961f,  0.55557023f,  0.19509032f,
                               -0.19509032f, -0.55557023f, -0.83146961f, -0.98078528f};
__constant__ float c_sz[8]  = { 0.19509032f,  0.55557023f,  0.83146961f,  0.98078528f,
                                0.98078528f,  0.83146961f,  0.55557023f,  0.19509032f};

__global__ __launch_bounds__(BLK, 1)
void aev_kernel(const float* __restrict__ coords, float* __restrict__ out, int n) {
    const int tid  = threadIdx.x;
    const int lane = tid & 31;
    const int wid  = tid >> 5;
    const int half = wid >> 4;            // 0 or 1: which atom this warp serves
    const int hw   = wid & 15;            // warp index within half
    const int t2   = tid & (HALF_T - 1);  // thread index within half
    const int i    = blockIdx.x * 2 + half;
    const bool active = (i < n);

    __shared__ float4 s_xyz[NATMAX];           // staged coords (shared by both halves)
    __shared__ float4 s_nbr[2][NBMAX2];        // per-half neighbor (ux,uy,uz,d)
    __shared__ float  s_fc[2][NBMAX2];         // per-half fc(RCA)
    __shared__ int    s_cnt[2][HWN];
    __shared__ int    s_tot[2];
    __shared__ float  sm_red[2][HWN * 17];     // radial staging, padded
    __shared__ float  sm_ang[2][HWN * 33];     // angular staging, padded
    __shared__ float  fin[2][48];

    // ---- stage coords once for both atoms ----
    if (tid < n) {
        s_xyz[tid] = make_float4(coords[3 * tid + 0], coords[3 * tid + 1],
                                 coords[3 * tid + 2], 0.f);
    }
    __syncthreads();

    float cix = 0.f, ciy = 0.f, ciz = 0.f;
    if (active) { cix = s_xyz[i].x; ciy = s_xyz[i].y; ciz = s_xyz[i].z; }

    // ---- build compacted RCA neighbor list per half (single pass, n <= HALF_T) ----
    bool nb = false;
    float dx = 0.f, dy = 0.f, dz = 0.f, d2 = 1.f;
    if (active && t2 < n && t2 != i) {
        float4 P = s_xyz[t2];
        dx = cix - P.x; dy = ciy - P.y; dz = ciz - P.z;
        d2 = dx * dx + dy * dy + dz * dz;
        nb = (d2 <= RCA * RCA);
    }
    unsigned bal = __ballot_sync(0xFFFFFFFFu, nb);
    if (lane == 0) s_cnt[half][hw] = __popc(bal);
    __syncthreads();
    if (hw == 0) {                        // warp 0 of each half scans its 16 counts
        int c = (lane < HWN) ? s_cnt[half][lane] : 0;
        int s = c;
        #pragma unroll
        for (int o = 1; o < HWN; o <<= 1) {
            int t = __shfl_up_sync(0xFFFFFFFFu, s, o);
            if (lane >= o) s += t;
        }
        if (lane < HWN) s_cnt[half][lane] = s - c;
        if (lane == HWN - 1) s_tot[half] = s;
    }
    __syncthreads();
    const int M = s_tot[half];
    if (nb) {
        int idx = s_cnt[half][hw] + __popc(bal & ((1u << lane) - 1u));
        float d = sqrtf(d2);
        float inv = 1.0f / d;
        s_nbr[half][idx] = make_float4(dx * inv, dy * inv, dz * inv, d);
        s_fc[half][idx]  = 0.5f * __cosf(PI_F * (1.0f / RCA) * d) + 0.5f;
    }
    __syncthreads();

    // ---- radial: bin-per-lane; each warp covers 2 j's per iter (half-warp split) ----
    {
        const int h = lane >> 4;
        const float shr = 0.9f + 0.26875f * (float)(lane & 15);
        float racc = 0.f;
        for (int it = 0; it * 2 * HWN < n; it++) {
            int j = (2 * it + h) * HWN + hw;
            bool valid = active && (j < n) && (j != i);
            int js = valid ? j : 0;
            float4 P = s_xyz[js];
            float ex = cix - P.x, ey = ciy - P.y, ez = ciz - P.z;
            float d = sqrtf(ex * ex + ey * ey + ez * ez);
            bool inr = valid && (d <= RCR);
            float fcr = 0.5f * __cosf(PI_F * (1.0f / RCR) * d) + 0.5f;
            float t = d - shr;
            float v = 0.25f * __expf(-ETA_R * t * t) * fcr;
            racc += inr ? v : 0.f;
        }
        racc += __shfl_xor_sync(0xFFFFFFFFu, racc, 16);
        if (lane < 16) sm_red[half][hw * 17 + lane] = racc;
    }

    // ---- angular: 4 pairs/warp-iter (pg = lane>>3), 8 zeta-bins/group, 4 ShfA accs ----
    {
        const int pg = lane >> 3;
        const int z  = lane & 7;
        const float czL = c_cz[z];
        const float szL = c_sz[z];
        float a0 = 0.f, a1 = 0.f, a2 = 0.f, a3 = 0.f;
        const int T = (M * (M - 1)) >> 1;   // unordered pairs j<k

        for (int p0 = hw * 4; p0 < T; p0 += HWN * 4) {
            int p = p0 + pg;
            bool ok = (p < T);
            int pc = ok ? p : 0;
            // triangle decode: jj s.t. jj(jj-1)/2 <= pc < jj(jj+1)/2
            int jj = (int)(0.5f * (1.0f + sqrtf(8.0f * (float)pc + 1.0f)));
            while (((jj * (jj - 1)) >> 1) > pc) --jj;
            while ((((jj + 1) * jj) >> 1) <= pc) ++jj;
            int kk = pc - ((jj * (jj - 1)) >> 1);

            float4 J = s_nbr[half][jj];
            float4 K = s_nbr[half][kk];
            float ct = 0.95f * (J.x * K.x + J.y * K.y + J.z * K.z);
            float st = sqrtf(fmaxf(1.0f - ct * ct, 0.0f));   // sin(acos(ct)) >= 0
            float davg = 0.5f * (J.w + K.w);
            float g = ok ? (s_fc[half][jj] * s_fc[half][kk]) : 0.f;
            // cos(theta - ShfZ) = ct*cos + st*sin; x = (1+cos)/2; x^32 by squaring
            float x = 0.5f + 0.5f * (ct * czL + st * szL);
            float x2 = x * x, x4 = x2 * x2, x8 = x4 * x4, x16 = x8 * x8;
            g *= x16 * x16;                                  // fcp * x^32
            // 4 Gaussians from 2 exps via the recurrence
            float t0 = davg - 0.9f;
            float e0 = __expf(-ETA_A * t0 * t0);
            float r  = __expf(TWO_ETA_D * t0);
            float m1 = r * QA;
            float e1 = e0 * m1;
            float m2 = m1 * QA2;
            float e2 = e1 * m2;
            float m3 = m2 * QA2;
            float e3 = e2 * m3;
            a0 += g * e0;
            a1 += g * e1;
            a2 += g * e2;
            a3 += g * e3;
        }

        // fold the 4 pair-groups; lanes 0-7 then hold bins (a, z=lane)
        a0 += __shfl_xor_sync(0xFFFFFFFFu, a0, 8);
        a0 += __shfl_xor_sync(0xFFFFFFFFu, a0, 16);
        a1 += __shfl_xor_sync(0xFFFFFFFFu, a1, 8);
        a1 += __shfl_xor_sync(0xFFFFFFFFu, a1, 16);
        a2 += __shfl_xor_sync(0xFFFFFFFFu, a2, 8);
        a2 += __shfl_xor_sync(0xFFFFFFFFu, a2, 16);
        a3 += __shfl_xor_sync(0xFFFFFFFFu, a3, 8);
        a3 += __shfl_xor_sync(0xFFFFFFFFu, a3, 16);
        if (lane < 8) {
            sm_ang[half][hw * 33 + 0  + lane] = a0;
            sm_ang[half][hw * 33 + 8  + lane] = a1;
            sm_ang[half][hw * 33 + 16 + lane] = a2;
            sm_ang[half][hw * 33 + 24 + lane] = a3;
        }
    }
    __syncthreads();

    // ---- cross-warp reductions: each warp reduces its half's bins over 16 source warps ----
    {
        // radial bin hw of this half
        float v = (lane < 16) ? sm_red[half][lane * 17 + hw] : 0.f;
        v += __shfl_xor_sync(0xFFFFFFFFu, v, 1);
        v += __shfl_xor_sync(0xFFFFFFFFu, v, 2);
        v += __shfl_xor_sync(0xFFFFFFFFu, v, 4);
        v += __shfl_xor_sync(0xFFFFFFFFu, v, 8);
        if (lane == 0) fin[half][hw] = v;
    }
    {
        // angular bins hw (lanes 0-15) and hw+16 (lanes 16-31)
        int bin = hw + ((lane >= 16) ? 16 : 0);
        float v = sm_ang[half][(lane & 15) * 33 + bin];
        v += __shfl_xor_sync(0xFFFFFFFFu, v, 1);
        v += __shfl_xor_sync(0xFFFFFFFFu, v, 2);
        v += __shfl_xor_sync(0xFFFFFFFFu, v, 4);
        v += __shfl_xor_sync(0xFFFFFFFFu, v, 8);
        if (lane == 0)  fin[half][16 + hw] = v;
        if (lane == 16) fin[half][32 + hw] = v;
    }
    __syncthreads();

    // ---- write the full 384-wide row per half, zeros in species padding ----
    if (active && t2 < AEV_W) {
        float v = 0.f;
        if (t2 < 16) v = fin[half][t2];
        else if (t2 >= 64 && t2 < 96) v = 2.0f * fin[half][16 + (t2 - 64)];  // ordered = 2*(j<k)
        out[i * AEV_W + t2] = v;
    }
}

extern "C" void kernel_launch(void* const* d_in, const int* in_sizes, int n_in,
                              void* d_out, int out_size) {
    const float* coords = (const float*)d_in[0];
    float* out = (float*)d_out;
    int n = in_sizes[0] / 3;
    int grid = (n + 1) / 2;
    aev_kernel<<<grid, BLK>>>(coords, out, n);
}

// round 11
// speedup vs baseline: 2.8893x; 1.2362x over previous
#include <cuda_runtime.h>
#include <math.h>

// ---- ANI-1x constants ----
#define RCR 5.2f
#define RCA 3.5f
#define ETA_R 16.0f
#define ETA_A 8.0f
#define PI_F 3.14159265358979323846f
#define AEV_W 384
#define BLK 1024
#define HALF_T 512        // threads per half (one atom per half)
#define HWN 16            // warps per half
#define NATMAX 512
#define NBMAX2 256

// Gaussian recurrence over the 4 equally spaced ShfA (0.9,1.55,2.2,2.85; delta=0.65):
// e_a = e0 * r^a * q^(a^2),  r = exp(2*eta*delta*t0), q = exp(-eta*delta^2)
#define QA   0.03404745f      // exp(-8*0.65^2)
#define QA2  0.001159229f     // QA^2
#define TWO_ETA_D 10.4f       // 2*8*0.65

// ShfZ = (2k+1)*pi/16 -> cos/sin are exact constants
__constant__ float c_cz[8]  = { 0.98078528f,  0.83146961f,  0.55557023f,  0.19509032f,
                               -0.19509032f, -0.55557023f, -0.83146961f, -0.98078528f};
__constant__ float c_sz[8]  = { 0.19509032f,  0.55557023f,  0.83146961f,  0.98078528f,
                                0.98078528f,  0.83146961f,  0.55557023f,  0.19509032f};

__global__ __launch_bounds__(BLK, 1)
void aev_kernel(const float* __restrict__ coords, float* __restrict__ out, int n) {
    const int tid  = threadIdx.x;
    const int lane = tid & 31;
    const int wid  = tid >> 5;
    const int half = wid >> 4;            // 0 or 1: which atom this warp serves
    const int hw   = wid & 15;            // warp index within half
    const int t2   = tid & (HALF_T - 1);  // thread index within half
    const int i    = blockIdx.x * 2 + half;
    const bool active = (i < n);

    __shared__ float4 s_xyz[NATMAX];           // staged coords (shared by both halves)
    __shared__ float4 s_nbr[2][NBMAX2];        // per-half RCA neighbor (ux,uy,uz,d)
    __shared__ float  s_fcA[2][NBMAX2];        // per-half fc(RCA)
    __shared__ float2 s_rad[2][NBMAX2];        // per-half RCR neighbor (d, 0.25*fc_r)
    __shared__ int    s_cntA[2][HWN];
    __shared__ int    s_cntR[2][HWN];
    __shared__ int    s_MA[2], s_MR[2];
    __shared__ float  sm_red[2][HWN * 17];     // radial staging, padded
    __shared__ float  sm_ang[2][HWN * 33];     // angular staging, padded
    __shared__ float  fin[2][48];

    // ---- stage coords once for both atoms ----
    if (tid < n) {
        s_xyz[tid] = make_float4(coords[3 * tid + 0], coords[3 * tid + 1],
                                 coords[3 * tid + 2], 0.f);
    }
    __syncthreads();

    float cix = 0.f, ciy = 0.f, ciz = 0.f;
    if (active) { cix = s_xyz[i].x; ciy = s_xyz[i].y; ciz = s_xyz[i].z; }

    // ---- single build pass: compact BOTH the RCA list and the RCR radial list ----
    bool inA = false, inR = false;
    float dx = 0.f, dy = 0.f, dz = 0.f, d2 = 1.f;
    if (active && t2 < n && t2 != i) {
        float4 P = s_xyz[t2];
        dx = cix - P.x; dy = ciy - P.y; dz = ciz - P.z;
        d2 = dx * dx + dy * dy + dz * dz;
        inR = (d2 <= RCR * RCR);
        inA = (d2 <= RCA * RCA);        // inA implies inR
    }
    unsigned balA = __ballot_sync(0xFFFFFFFFu, inA);
    unsigned balR = __ballot_sync(0xFFFFFFFFu, inR);
    if (lane == 0) { s_cntA[half][hw] = __popc(balA); s_cntR[half][hw] = __popc(balR); }
    __syncthreads();
    if (hw == 0) {   // dual segmented scan: lanes 0-15 scan cntA, lanes 16-31 scan cntR
        int l16 = lane & 15;
        int c = (lane < 16) ? s_cntA[half][l16] : s_cntR[half][l16];
        int s = c;
        #pragma unroll
        for (int o = 1; o < 16; o <<= 1) {
            int t = __shfl_up_sync(0xFFFFFFFFu, s, o, 16);
            if (l16 >= o) s += t;
        }
        if (lane < 16) { s_cntA[half][l16] = s - c; if (l16 == 15) s_MA[half] = s; }
        else           { s_cntR[half][l16] = s - c; if (l16 == 15) s_MR[half] = s; }
    }
    __syncthreads();
    const int MA = s_MA[half];
    const int MR = s_MR[half];
    if (inR) {
        unsigned lml = (1u << lane) - 1u;
        float d = sqrtf(d2);
        int idxR = s_cntR[half][hw] + __popc(balR & lml);
        float fc025 = 0.25f * (0.5f * __cosf(PI_F * (1.0f / RCR) * d) + 0.5f);
        s_rad[half][idxR] = make_float2(d, fc025);
        if (inA) {
            int idxA = s_cntA[half][hw] + __popc(balA & lml);
            float inv = 1.0f / d;
            s_nbr[half][idxA] = make_float4(dx * inv, dy * inv, dz * inv, d);
            s_fcA[half][idxA] = 0.5f * __cosf(PI_F * (1.0f / RCA) * d) + 0.5f;
        }
    }
    __syncthreads();

    // ---- radial over the compacted RCR list: bin-per-lane, 2 j's per warp-iter ----
    {
        const int h = lane >> 4;
        const float shr = 0.9f + 0.26875f * (float)(lane & 15);
        float racc = 0.f;
        for (int it = 0; it * 2 * HWN < MR; it++) {
            int j = (2 * it + h) * HWN + hw;
            bool v = (j < MR);
            float2 R = s_rad[half][v ? j : 0];
            float t = R.x - shr;
            float e = R.y * __expf(-ETA_R * t * t);
            racc += v ? e : 0.f;
        }
        racc += __shfl_xor_sync(0xFFFFFFFFu, racc, 16);
        if (lane < 16) sm_red[half][hw * 17 + lane] = racc;
    }

    // ---- angular: snake-ordered rows (perfect balance, no decode), J hoisted per row,
    //      4 pairs/iter (pg = lane>>3), 8 zeta-bins/group, 4 ShfA accumulators ----
    {
        const int pg = lane >> 3;
        const int z  = lane & 7;
        const float czL = c_cz[z];
        const float szL = c_sz[z];
        float a0 = 0.f, a1 = 0.f, a2 = 0.f, a3 = 0.f;
        const int M = MA;

        for (int r = 0;; r++) {
            int off = (r & 1) ? (HWN - 1 - hw) : hw;
            int jj = M - 1 - (r * HWN + off);
            if (jj < 1) break;
            float4 J = s_nbr[half][jj];
            float jfc = s_fcA[half][jj];
            for (int kb = 0; kb < jj; kb += 4) {
                int kk = kb + pg;
                bool ok = (kk < jj);
                int kc = ok ? kk : 0;
                float4 K = s_nbr[half][kc];
                float g = ok ? (jfc * s_fcA[half][kc]) : 0.f;
                float ct = 0.95f * (J.x * K.x + J.y * K.y + J.z * K.z);
                float st = sqrtf(fmaxf(1.0f - ct * ct, 0.0f));   // sin(acos(ct)) >= 0
                float davg = 0.5f * (J.w + K.w);
                // cos(theta - ShfZ) = ct*cos + st*sin; x = (1+cos)/2; x^32 by squaring
                float x = 0.5f + 0.5f * (ct * czL + st * szL);
                float x2 = x * x, x4 = x2 * x2, x8 = x4 * x4, x16 = x8 * x8;
                g *= x16 * x16;                                  // fcp * x^32
                // 4 Gaussians from 2 exps via the recurrence
                float t0 = davg - 0.9f;
                float e0 = __expf(-ETA_A * t0 * t0);
                float rr = __expf(TWO_ETA_D * t0);
                float m1 = rr * QA;
                float e1 = e0 * m1;
                float m2 = m1 * QA2;
                float e2 = e1 * m2;
                float m3 = m2 * QA2;
                float e3 = e2 * m3;
                a0 += g * e0;
                a1 += g * e1;
                a2 += g * e2;
                a3 += g * e3;
            }
        }

        // fold the 4 pair-groups; lanes 0-7 then hold bins (a, z=lane)
        a0 += __shfl_xor_sync(0xFFFFFFFFu, a0, 8);
        a0 += __shfl_xor_sync(0xFFFFFFFFu, a0, 16);
        a1 += __shfl_xor_sync(0xFFFFFFFFu, a1, 8);
        a1 += __shfl_xor_sync(0xFFFFFFFFu, a1, 16);
        a2 += __shfl_xor_sync(0xFFFFFFFFu, a2, 8);
        a2 += __shfl_xor_sync(0xFFFFFFFFu, a2, 16);
        a3 += __shfl_xor_sync(0xFFFFFFFFu, a3, 8);
        a3 += __shfl_xor_sync(0xFFFFFFFFu, a3, 16);
        if (lane < 8) {
            sm_ang[half][hw * 33 + 0  + lane] = a0;
            sm_ang[half][hw * 33 + 8  + lane] = a1;
            sm_ang[half][hw * 33 + 16 + lane] = a2;
            sm_ang[half][hw * 33 + 24 + lane] = a3;
        }
    }
    __syncthreads();

    // ---- cross-warp reductions: each warp reduces its half's bins over 16 source warps ----
    {
        float v = (lane < 16) ? sm_red[half][lane * 17 + hw] : 0.f;
        v += __shfl_xor_sync(0xFFFFFFFFu, v, 1);
        v += __shfl_xor_sync(0xFFFFFFFFu, v, 2);
        v += __shfl_xor_sync(0xFFFFFFFFu, v, 4);
        v += __shfl_xor_sync(0xFFFFFFFFu, v, 8);
        if (lane == 0) fin[half][hw] = v;
    }
    {
        int bin = hw + ((lane >= 16) ? 16 : 0);
        float v = sm_ang[half][(lane & 15) * 33 + bin];
        v += __shfl_xor_sync(0xFFFFFFFFu, v, 1);
        v += __shfl_xor_sync(0xFFFFFFFFu, v, 2);
        v += __shfl_xor_sync(0xFFFFFFFFu, v, 4);
        v += __shfl_xor_sync(0xFFFFFFFFu, v, 8);
        if (lane == 0)  fin[half][16 + hw] = v;
        if (lane == 16) fin[half][32 + hw] = v;
    }
    __syncthreads();

    // ---- write the full 384-wide row per half, zeros in species padding ----
    if (active && t2 < AEV_W) {
        float v = 0.f;
        if (t2 < 16) v = fin[half][t2];
        else if (t2 >= 64 && t2 < 96) v = 2.0f * fin[half][16 + (t2 - 64)];  // ordered = 2*(j<k)
        out[i * AEV_W + t2] = v;
    }
}

extern "C" void kernel_launch(void* const* d_in, const int* in_sizes, int n_in,
                              void* d_out, int out_size) {
    const float* coords = (const float*)d_in[0];
    float* out = (float*)d_out;
    int n = in_sizes[0] / 3;
    int grid = (n + 1) / 2;
    aev_kernel<<<grid, BLK>>>(coords, out, n);
}